// round 6
// baseline (speedup 1.0000x reference)
#include <cuda_runtime.h>
#include <math.h>

#define Bsz 256
#define Xd  256
#define Hd  512
#define Rd  128
#define Md  128
#define Td  256
#define XHD 768      // X+H
#define CATD 896     // X+H+R
#define NPRE 2176    // R+4H columns of W_full
#define NG1 640      // R+H
#define ODIM 640

typedef unsigned long long ull;

// persistent state / scratch (device globals; no allocation)
__device__ float g_c[Bsz*Hd];
__device__ float g_hmem[Bsz*Md*Rd];
__device__ float g_cc [Bsz*CATD];   // unscaled concat [x, c, h_entry]
__device__ float g_cc2[Bsz*CATD];   // scaled concat
__device__ float g_hent[Bsz*Rd];
__device__ int   g_sel[Bsz];
__device__ float g_fcwxT[Xd*Md];    // fc_w x-part transposed (k-major)
__device__ float g_wcomb[Hd*256];   // [k][0:128]=fc_w c-part^T, [k][128:256]=trans_w^T
__device__ float g_xh[Td*Bsz*Md];   // precomputed x-part of head (+fc_b)

__device__ __forceinline__ float sigf(float v){ return 1.0f/(1.0f+expf(-v)); }
__device__ __forceinline__ ull pack2(float v){ ull r; asm("mov.b64 %0, {%1, %1};" : "=l"(r) : "f"(v)); return r; }
__device__ __forceinline__ void ffma2(ull &d, ull a, ull b){ asm("fma.rn.f32x2 %0, %1, %2, %0;" : "+l"(d) : "l"(a), "l"(b)); }
__device__ __forceinline__ float2 unpk(ull v){ float2 f; asm("mov.b64 {%0, %1}, %2;" : "=f"(f.x), "=f"(f.y) : "l"(v)); return f; }

// ---------------- init: transposes + combined weights + c0 + hmem0 ----------------
__global__ void k_init(const float* __restrict__ fc_w, const float* __restrict__ trans_w,
                       const float* __restrict__ c_bias, const float* __restrict__ hmem_bias)
{
    int idx = blockIdx.x*blockDim.x + threadIdx.x;
    if (idx < Bsz*Md*Rd) g_hmem[idx] = hmem_bias[idx & (Md*Rd-1)];
    if (idx < Bsz*Hd)    g_c[idx] = tanhf(c_bias[idx & (Hd-1)]);
    if (idx < Xd*Md) {               // fcwxT[k][m] = fc_w[m][k], k<256
        int k = idx >> 7, m = idx & 127;
        g_fcwxT[idx] = fc_w[m*XHD + k];
    }
    if (idx < Hd*256) {              // wcomb[k][c]
        int k = idx >> 8, c = idx & 255;
        g_wcomb[idx] = (c < 128) ? fc_w[c*XHD + Xd + k]
                                 : trans_w[(c-128)*Hd + k];
    }
}

// ---------------- Xh precompute: (T*B,128) = x(T*B,256) @ fcwxT + fc_b -------------
__global__ __launch_bounds__(256) void k_xhead(const float* __restrict__ x,
                                               const float* __restrict__ fc_b)
{
    __shared__ __align__(16) float As[16][68];
    __shared__ __align__(16) float Bs[16][128];
    const int tid = threadIdx.x;
    const int rb = blockIdx.x * 64;
    const int tm = tid >> 5;        // 0..7 rows group of 8
    const int tn = tid & 31;        // 0..31 cols group of 4 (2 pairs)

    ull acc[8][2] = {};

    const int ar = tid >> 2, akq = tid & 3;
    const float* Ap = x + (size_t)(rb + ar)*Xd + akq*4;
    const int bk = tid >> 4, bm = tid & 15;
    const float* Bp = g_fcwxT + (size_t)bk*Md + bm*8;

    float4 pa = *(const float4*)Ap;
    float4 pb0 = *(const float4*)(Bp);
    float4 pb1 = *(const float4*)(Bp + 4);

    for (int kt = 0; kt < Xd/16; kt++) {
        As[akq*4+0][ar]=pa.x; As[akq*4+1][ar]=pa.y; As[akq*4+2][ar]=pa.z; As[akq*4+3][ar]=pa.w;
        *(float4*)&Bs[bk][bm*8]   = pb0;
        *(float4*)&Bs[bk][bm*8+4] = pb1;
        __syncthreads();
        if (kt+1 < Xd/16) {
            int k0 = (kt+1)*16;
            pa  = *(const float4*)(Ap + k0);
            pb0 = *(const float4*)(Bp + (size_t)k0*Md);
            pb1 = *(const float4*)(Bp + (size_t)k0*Md + 4);
        }
        #pragma unroll
        for (int kk = 0; kk < 16; kk++) {
            float4 a0 = *(const float4*)&As[kk][tm*8];
            float4 a1 = *(const float4*)&As[kk][tm*8+4];
            ulonglong2 bq = *(const ulonglong2*)&Bs[kk][tn*4];
            float a_[8] = {a0.x,a0.y,a0.z,a0.w,a1.x,a1.y,a1.z,a1.w};
            #pragma unroll
            for (int i=0;i<8;i++){
                ull ap = pack2(a_[i]);
                ffma2(acc[i][0], ap, bq.x);
                ffma2(acc[i][1], ap, bq.y);
            }
        }
        __syncthreads();
    }
    float4 fb = *(const float4*)(fc_b + tn*4);
    #pragma unroll
    for (int i=0;i<8;i++){
        int row = rb + tm*8 + i;
        float2 l0 = unpk(acc[i][0]), l1 = unpk(acc[i][1]);
        float4 o = { l0.x+fb.x, l0.y+fb.y, l1.x+fb.z, l1.y+fb.w };
        *(float4*)(g_xh + (size_t)row*Md + tn*4) = o;
    }
}

// ---------------- gates1 GEMM: cc(256x896) @ W1(896x640), fused sigmoid -> cc2 ------
// BM=32, BN=64, full K=896, 256 threads, thread tile 2x4 (f32x2). grid (8,10)=80.
__global__ __launch_bounds__(256) void k_gates(const float* __restrict__ W1,
                                               const float* __restrict__ bias1)
{
    __shared__ __align__(16) float As[2][16][34];
    __shared__ __align__(16) float Bs[2][16][64];
    const int tid = threadIdx.x;
    const int rb = blockIdx.x * 32;
    const int nb = blockIdx.y * 64;
    const int tm = tid >> 4;       // 0..15, rows tm*2, tm*2+1
    const int tn = tid & 15;       // cols tn*4 (2 pairs)

    ull acc[2][2] = {};

    const int ar = tid >> 2, akq = tid & 3;            // tid<128 loads A
    const float* Ap = g_cc + (size_t)(rb + ar)*CATD + akq*4;
    const int bk = tid >> 4, bn4 = tid & 15;           // 16x16 = 256 loads B
    const float* Bp = W1 + (size_t)bk*NG1 + nb + bn4*4;

    float4 pa = {0,0,0,0};
    if (tid < 128) pa = *(const float4*)Ap;
    float4 pb = *(const float4*)Bp;

    if (tid < 128){
        As[0][akq*4+0][ar]=pa.x; As[0][akq*4+1][ar]=pa.y;
        As[0][akq*4+2][ar]=pa.z; As[0][akq*4+3][ar]=pa.w;
    }
    *(float4*)&Bs[0][bk][bn4*4] = pb;
    __syncthreads();

    for (int kt = 0; kt < CATD/16; kt++) {
        const int p = kt & 1;
        if (kt+1 < CATD/16) {
            int k0 = (kt+1)*16;
            if (tid < 128) pa = *(const float4*)(Ap + k0);
            pb = *(const float4*)(Bp + (size_t)k0*NG1);
        }
        #pragma unroll
        for (int kk = 0; kk < 16; kk++) {
            float2 a2 = *(const float2*)&As[p][kk][tm*2];
            ulonglong2 bq = *(const ulonglong2*)&Bs[p][kk][tn*4];
            ull a0 = pack2(a2.x), a1 = pack2(a2.y);
            ffma2(acc[0][0], a0, bq.x); ffma2(acc[0][1], a0, bq.y);
            ffma2(acc[1][0], a1, bq.x); ffma2(acc[1][1], a1, bq.y);
        }
        if (kt+1 < CATD/16) {
            const int q = p^1;
            if (tid < 128){
                As[q][akq*4+0][ar]=pa.x; As[q][akq*4+1][ar]=pa.y;
                As[q][akq*4+2][ar]=pa.z; As[q][akq*4+3][ar]=pa.w;
            }
            *(float4*)&Bs[q][bk][bn4*4] = pb;
        }
        __syncthreads();
    }
    const int n0 = nb + tn*4;
    float4 bv = *(const float4*)(bias1 + n0);
    #pragma unroll
    for (int i=0;i<2;i++){
        int row = rb + tm*2 + i;
        float2 l0 = unpk(acc[i][0]), l1 = unpk(acc[i][1]);
        float4 ccv = *(const float4*)(g_cc + (size_t)row*CATD + Xd + n0);
        float4 o;
        o.x = ccv.x * sigf(l0.x + bv.x);
        o.y = ccv.y * sigf(l0.y + bv.y);
        o.z = ccv.z * sigf(l1.x + bv.z);
        o.w = ccv.w * sigf(l1.y + bv.w);
        *(float4*)(g_cc2 + (size_t)row*CATD + Xd + n0) = o;
    }
}

// ---------------- big GEMM with fused LSTM / r epilogue (f32x2) ---------------------
// 256 threads, 64 rows x 16 quads, thread tile 4x4, double-buffered. grid (4,34).
__global__ __launch_bounds__(256) void k_big(const float* __restrict__ Wf,
                                             const float* __restrict__ bias,
                                             float* __restrict__ out, int t)
{
    __shared__ __align__(16) float As[2][16][68];
    __shared__ __align__(16) float Bs[2][16][64];
    const int tid = threadIdx.x;
    const int rb = blockIdx.x * 64;
    const int y = blockIdx.y;
    const bool isOm = (y >= 32);
    const int cb = isOm ? (2048 + (y-32)*64) : y*16;
    const int S  = isOm ? 16 : 512;
    const int tm = tid >> 4;   // rows group of 4
    const int tx = tid & 15;   // quad index

    ull acc[4][2] = {};

    const int ar = tid >> 2, akq = tid & 3;
    const float* Ap = g_cc2 + (size_t)(rb + ar)*CATD + akq*4;
    const int bk = tid >> 4, bg = (tid >> 2) & 3, bq4 = tid & 3;
    const float* Bp = Wf + (size_t)bk*NPRE + cb + S*bg + bq4*4;

    float4 pa = *(const float4*)Ap;
    float4 pb = *(const float4*)Bp;

    As[0][akq*4+0][ar]=pa.x; As[0][akq*4+1][ar]=pa.y;
    As[0][akq*4+2][ar]=pa.z; As[0][akq*4+3][ar]=pa.w;
    Bs[0][bk][(bq4*4+0)*4+bg]=pb.x; Bs[0][bk][(bq4*4+1)*4+bg]=pb.y;
    Bs[0][bk][(bq4*4+2)*4+bg]=pb.z; Bs[0][bk][(bq4*4+3)*4+bg]=pb.w;
    __syncthreads();

    for (int kt = 0; kt < CATD/16; kt++) {
        const int p = kt & 1;
        if (kt+1 < CATD/16) {
            int k0 = (kt+1)*16;
            pa = *(const float4*)(Ap + k0);
            pb = *(const float4*)(Bp + (size_t)k0*NPRE);
        }
        #pragma unroll
        for (int kk=0; kk<16; kk++){
            float4 av = *(const float4*)&As[p][kk][tm*4];
            ulonglong2 bq = *(const ulonglong2*)&Bs[p][kk][tx*4];
            ull a0 = pack2(av.x), a1 = pack2(av.y), a2 = pack2(av.z), a3 = pack2(av.w);
            ffma2(acc[0][0], a0, bq.x); ffma2(acc[0][1], a0, bq.y);
            ffma2(acc[1][0], a1, bq.x); ffma2(acc[1][1], a1, bq.y);
            ffma2(acc[2][0], a2, bq.x); ffma2(acc[2][1], a2, bq.y);
            ffma2(acc[3][0], a3, bq.x); ffma2(acc[3][1], a3, bq.y);
        }
        if (kt+1 < CATD/16) {
            const int q = p^1;
            As[q][akq*4+0][ar]=pa.x; As[q][akq*4+1][ar]=pa.y;
            As[q][akq*4+2][ar]=pa.z; As[q][akq*4+3][ar]=pa.w;
            Bs[q][bk][(bq4*4+0)*4+bg]=pb.x; Bs[q][bk][(bq4*4+1)*4+bg]=pb.y;
            Bs[q][bk][(bq4*4+2)*4+bg]=pb.z; Bs[q][bk][(bq4*4+3)*4+bg]=pb.w;
        }
        __syncthreads();
    }

    if (!isOm) {
        const int n = cb + tx;
        const float bi = bias[n], bj = bias[n+512], bf = bias[n+1024], bo = bias[n+1536];
        #pragma unroll
        for (int i=0;i<4;i++){
            int row = rb + tm*4 + i;
            float2 ij = unpk(acc[i][0]), fo = unpk(acc[i][1]);
            float c_old = g_c[row*Hd + n];
            float iv = ij.x+bi, jv = ij.y+bj, fv = fo.x+bf, ov = fo.y+bo;
            float nc = tanhf(c_old*sigf(fv + 1.0f) + sigf(iv)*tanhf(jv));
            g_c[row*Hd + n] = nc;
            out[(size_t)t*Bsz*ODIM + (size_t)row*ODIM + n] = nc * sigf(ov);
        }
    } else {
        #pragma unroll
        for (int i=0;i<4;i++){
            int row = rb + tm*4 + i;
            float2 g01 = unpk(acc[i][0]), g23 = unpk(acc[i][1]);
            float gv[4] = {g01.x, g01.y, g23.x, g23.y};
            #pragma unroll
            for (int g=0; g<4; g++){
                int mcol = (cb - 2048) + 16*g + tx;
                float rv = g_hent[row*Rd + mcol] * sigf(gv[g] + bias[2048 + mcol]);
                out[(size_t)t*Bsz*ODIM + (size_t)row*ODIM + Hd + mcol] = rv;
            }
        }
    }
}

// ---------------- tail: [head_c | wv] GEMM (K=512) + argmax + hmem scatter + gather
// grid 64 blocks x 256 threads; 4 batch rows per block. t in [-1, T-2].
__global__ __launch_bounds__(256) void k_tail(const float* __restrict__ x,
                                              const float* __restrict__ noise,
                                              const float* __restrict__ trans_b,
                                              int t)
{
    __shared__ float s_c[4][512];
    __shared__ float s_head[4][132];
    __shared__ float s_wv[4][132];
    __shared__ int   s_sel[4], s_selold[4];
    const int tid = threadIdx.x;
    const int warp = tid >> 5, lane = tid & 31;
    const int b0 = blockIdx.x * 4;
    const int tn = t + 1;

    #pragma unroll
    for (int j=0;j<2;j++){ int i = tid + 256*j; int r = i>>7, cc = i&127;
      *(float4*)&s_c[r][cc*4] = *(const float4*)(g_c + (b0+r)*Hd + cc*4); }
    if (tid < 4) s_selold[tid] = g_sel[b0+tid];
    __syncthreads();

    // GEMM: 4 rows x 256 cols (128 head_c | 128 wv), K=512 from s_c
    {
        const int rg = tid >> 6;          // 0..3 row
        const int c4 = (tid & 63) * 4;    // col group
        ull acc0 = 0, acc1 = 0;
        const float* wp = g_wcomb + c4;
        #pragma unroll 4
        for (int k = 0; k < Hd; k++){
            ull ap = pack2(s_c[rg][k]);
            ulonglong2 wq = *(const ulonglong2*)(wp + (size_t)k*256);
            ffma2(acc0, ap, wq.x);
            ffma2(acc1, ap, wq.y);
        }
        float2 l0 = unpk(acc0), l1 = unpk(acc1);
        float4 a = { l0.x, l0.y, l1.x, l1.y };
        if (c4 < 128) {
            float4 xh = *(const float4*)(g_xh + ((size_t)tn*Bsz + b0 + rg)*Md + c4);
            a.x += xh.x; a.y += xh.y; a.z += xh.z; a.w += xh.w;
            *(float4*)&s_head[rg][c4] = a;
        } else {
            int m4 = c4 - 128;
            float4 tb = *(const float4*)(trans_b + m4);
            a.x += tb.x; a.y += tb.y; a.z += tb.z; a.w += tb.w;
            *(float4*)&s_wv[rg][m4] = a;
        }
    }
    __syncthreads();

    // warps 0-3: gumbel + argmax; warps 4-7: hmem row write (t>=0)
    if (warp < 4) {
        int r = warp;
        float4 hv = *(const float4*)&s_head[r][lane*4];
        float4 nz = *(const float4*)(noise + ((size_t)tn*Bsz + b0 + r)*Md + lane*4);
        float v[4];
        v[0] = hv.x - logf(1e-20f - logf(1e-20f + nz.x));
        v[1] = hv.y - logf(1e-20f - logf(1e-20f + nz.y));
        v[2] = hv.z - logf(1e-20f - logf(1e-20f + nz.z));
        v[3] = hv.w - logf(1e-20f - logf(1e-20f + nz.w));
        float best = v[0]; int bi = lane*4;
        #pragma unroll
        for (int c=1;c<4;c++) if (v[c] > best){ best = v[c]; bi = lane*4+c; }
        #pragma unroll
        for (int off=16; off; off>>=1){
            float ov = __shfl_xor_sync(0xffffffffu, best, off);
            int   oi = __shfl_xor_sync(0xffffffffu, bi,   off);
            if (ov > best || (ov == best && oi < bi)){ best = ov; bi = oi; }
        }
        if (lane == 0) s_sel[r] = bi;
    } else if (t >= 0) {
        int r = warp - 4;
        float4 wv = *(const float4*)&s_wv[r][lane*4];
        int idx = (t < Md) ? t : s_selold[r];
        *(float4*)(g_hmem + ((size_t)(b0+r)*Md + idx)*Rd + lane*4) = wv;
    }
    __syncthreads();

    // gather h_entry for t+1, write cc / cc2 / sel
    if (warp < 4) {
        int r = warp;
        int sel = s_sel[r];
        float4 h4 = *(const float4*)(g_hmem + ((size_t)(b0+r)*Md + sel)*Rd + lane*4);
        *(float4*)(g_hent + (b0+r)*Rd + lane*4) = h4;
        *(float4*)(g_cc + (size_t)(b0+r)*CATD + XHD + lane*4) = h4;
        if (lane == 0) g_sel[b0+r] = sel;
    }
    { int r = tid>>6, cc = tid&63;
      float4 xv = *(const float4*)(x + ((size_t)tn*Bsz + b0 + r)*Xd + cc*4);
      *(float4*)(g_cc  + (size_t)(b0+r)*CATD + cc*4) = xv;
      *(float4*)(g_cc2 + (size_t)(b0+r)*CATD + cc*4) = xv; }
    #pragma unroll
    for (int j=0;j<2;j++){ int i = tid + 256*j; int r = i>>7, cc = i&127;
      *(float4*)(g_cc + (size_t)(b0+r)*CATD + Xd + cc*4) = *(const float4*)&s_c[r][cc*4]; }
}

extern "C" void kernel_launch(void* const* d_in, const int* in_sizes, int n_in,
                              void* d_out, int out_size)
{
    const float* x       = (const float*)d_in[0];
    const float* noise   = (const float*)d_in[1];
    const float* W_full  = (const float*)d_in[2];
    const float* bias    = (const float*)d_in[3];
    const float* W_full1 = (const float*)d_in[4];
    const float* bias1   = (const float*)d_in[5];
    const float* fc_w    = (const float*)d_in[6];
    const float* fc_b    = (const float*)d_in[7];
    const float* trans_w = (const float*)d_in[8];
    const float* trans_b = (const float*)d_in[9];
    const float* c_bias  = (const float*)d_in[10];
    const float* hmem_b  = (const float*)d_in[11];
    float* out = (float*)d_out;

    const int initN = Bsz*Md*Rd;
    k_init<<<(initN + 255)/256, 256>>>(fc_w, trans_w, c_bias, hmem_b);
    k_xhead<<<Td*Bsz/64, 256>>>(x, fc_b);
    k_tail<<<64, 256>>>(x, noise, trans_b, -1);   // prologue: head/argmax for t=0
    for (int t = 0; t < Td; t++){
        k_gates<<<dim3(8,10), 256>>>(W_full1, bias1);
        k_big  <<<dim3(4,34), 256>>>(W_full, bias, out, t);
        if (t < Td-1) k_tail<<<64, 256>>>(x, noise, trans_b, t);
    }
}

// round 7
// speedup vs baseline: 1.0030x; 1.0030x over previous
#include <cuda_runtime.h>
#include <math.h>

#define Bsz 256
#define Xd  256
#define Hd  512
#define Rd  128
#define Md  128
#define Td  256
#define XHD 768      // X+H
#define CATD 896     // X+H+R
#define NPRE 2176    // R+4H columns of W_full
#define NG1 640      // R+H
#define ODIM 640

typedef unsigned long long ull;

// persistent state / scratch (device globals; no allocation)
__device__ float g_c[Bsz*Hd];
__device__ float g_hmem[Bsz*Md*Rd];
__device__ float g_cc [Bsz*CATD];   // unscaled concat [x, c, h_entry]
__device__ float g_cc2[Bsz*CATD];   // scaled concat
__device__ float g_hent[Bsz*Rd];
__device__ int   g_sel[Bsz];
__device__ float g_fcwxT[Xd*Md];    // fc_w x-part transposed (k-major)
__device__ float g_wcomb[Hd*256];   // [k][0:128]=fc_w c-part^T, [k][128:256]=trans_w^T
__device__ float g_xh[Td*Bsz*Md];   // precomputed x-part of head (+fc_b)

__device__ __forceinline__ float sigf(float v){ return 1.0f/(1.0f+expf(-v)); }
__device__ __forceinline__ ull pack2(float v){ ull r; asm("mov.b64 %0, {%1, %1};" : "=l"(r) : "f"(v)); return r; }
__device__ __forceinline__ void ffma2(ull &d, ull a, ull b){ asm("fma.rn.f32x2 %0, %1, %2, %0;" : "+l"(d) : "l"(a), "l"(b)); }
__device__ __forceinline__ float2 unpk(ull v){ float2 f; asm("mov.b64 {%0, %1}, %2;" : "=f"(f.x), "=f"(f.y) : "l"(v)); return f; }

// ---------------- init: transposes + combined weights + c0 + hmem0 ----------------
__global__ void k_init(const float* __restrict__ fc_w, const float* __restrict__ trans_w,
                       const float* __restrict__ c_bias, const float* __restrict__ hmem_bias)
{
    int idx = blockIdx.x*blockDim.x + threadIdx.x;
    if (idx < Bsz*Md*Rd) g_hmem[idx] = hmem_bias[idx & (Md*Rd-1)];
    if (idx < Bsz*Hd)    g_c[idx] = tanhf(c_bias[idx & (Hd-1)]);
    if (idx < Xd*Md) {               // fcwxT[k][m] = fc_w[m][k], k<256
        int k = idx >> 7, m = idx & 127;
        g_fcwxT[idx] = fc_w[m*XHD + k];
    }
    if (idx < Hd*256) {              // wcomb[k][c]
        int k = idx >> 8, c = idx & 255;
        g_wcomb[idx] = (c < 128) ? fc_w[c*XHD + Xd + k]
                                 : trans_w[(c-128)*Hd + k];
    }
}

// ---------------- Xh precompute: (T*B,128) = x(T*B,256) @ fcwxT + fc_b -------------
__global__ __launch_bounds__(256) void k_xhead(const float* __restrict__ x,
                                               const float* __restrict__ fc_b)
{
    __shared__ __align__(16) float As[16][68];
    __shared__ __align__(16) float Bs[16][128];
    const int tid = threadIdx.x;
    const int rb = blockIdx.x * 64;
    const int tm = tid >> 5;        // 0..7 rows group of 8
    const int tn = tid & 31;        // 0..31 cols group of 4 (2 pairs)

    ull acc[8][2] = {};

    const int ar = tid >> 2, akq = tid & 3;
    const float* Ap = x + (size_t)(rb + ar)*Xd + akq*4;
    const int bk = tid >> 4, bm = tid & 15;
    const float* Bp = g_fcwxT + (size_t)bk*Md + bm*8;

    float4 pa = *(const float4*)Ap;
    float4 pb0 = *(const float4*)(Bp);
    float4 pb1 = *(const float4*)(Bp + 4);

    for (int kt = 0; kt < Xd/16; kt++) {
        As[akq*4+0][ar]=pa.x; As[akq*4+1][ar]=pa.y; As[akq*4+2][ar]=pa.z; As[akq*4+3][ar]=pa.w;
        *(float4*)&Bs[bk][bm*8]   = pb0;
        *(float4*)&Bs[bk][bm*8+4] = pb1;
        __syncthreads();
        if (kt+1 < Xd/16) {
            int k0 = (kt+1)*16;
            pa  = *(const float4*)(Ap + k0);
            pb0 = *(const float4*)(Bp + (size_t)k0*Md);
            pb1 = *(const float4*)(Bp + (size_t)k0*Md + 4);
        }
        #pragma unroll
        for (int kk = 0; kk < 16; kk++) {
            float4 a0 = *(const float4*)&As[kk][tm*8];
            float4 a1 = *(const float4*)&As[kk][tm*8+4];
            ulonglong2 bq = *(const ulonglong2*)&Bs[kk][tn*4];
            float a_[8] = {a0.x,a0.y,a0.z,a0.w,a1.x,a1.y,a1.z,a1.w};
            #pragma unroll
            for (int i=0;i<8;i++){
                ull ap = pack2(a_[i]);
                ffma2(acc[i][0], ap, bq.x);
                ffma2(acc[i][1], ap, bq.y);
            }
        }
        __syncthreads();
    }
    float4 fb = *(const float4*)(fc_b + tn*4);
    #pragma unroll
    for (int i=0;i<8;i++){
        int row = rb + tm*8 + i;
        float2 l0 = unpk(acc[i][0]), l1 = unpk(acc[i][1]);
        float4 o = { l0.x+fb.x, l0.y+fb.y, l1.x+fb.z, l1.y+fb.w };
        *(float4*)(g_xh + (size_t)row*Md + tn*4) = o;
    }
}

// ---------------- gates1 GEMM: cc(256x896) @ W1(896x640), fused sigmoid -> cc2 ------
// BM=32, BN=64, full K=896, 256 threads, thread tile 2x4 (f32x2). grid (8,10)=80.
__global__ __launch_bounds__(256) void k_gates(const float* __restrict__ W1,
                                               const float* __restrict__ bias1)
{
    __shared__ __align__(16) float As[2][16][34];
    __shared__ __align__(16) float Bs[2][16][64];
    const int tid = threadIdx.x;
    const int rb = blockIdx.x * 32;
    const int nb = blockIdx.y * 64;
    const int tm = tid >> 4;       // 0..15, rows tm*2, tm*2+1
    const int tn = tid & 15;       // cols tn*4 (2 pairs)

    ull acc[2][2] = {};

    const int ar = tid >> 2, akq = tid & 3;            // tid<128 loads A
    const float* Ap = g_cc + (size_t)(rb + ar)*CATD + akq*4;
    const int bk = tid >> 4, bn4 = tid & 15;           // 16x16 = 256 loads B
    const float* Bp = W1 + (size_t)bk*NG1 + nb + bn4*4;

    float4 pa = {0,0,0,0};
    if (tid < 128) pa = *(const float4*)Ap;
    float4 pb = *(const float4*)Bp;

    if (tid < 128){
        As[0][akq*4+0][ar]=pa.x; As[0][akq*4+1][ar]=pa.y;
        As[0][akq*4+2][ar]=pa.z; As[0][akq*4+3][ar]=pa.w;
    }
    *(float4*)&Bs[0][bk][bn4*4] = pb;
    __syncthreads();

    for (int kt = 0; kt < CATD/16; kt++) {
        const int p = kt & 1;
        if (kt+1 < CATD/16) {
            int k0 = (kt+1)*16;
            if (tid < 128) pa = *(const float4*)(Ap + k0);
            pb = *(const float4*)(Bp + (size_t)k0*NG1);
        }
        #pragma unroll
        for (int kk = 0; kk < 16; kk++) {
            float2 a2 = *(const float2*)&As[p][kk][tm*2];
            ulonglong2 bq = *(const ulonglong2*)&Bs[p][kk][tn*4];
            ull a0 = pack2(a2.x), a1 = pack2(a2.y);
            ffma2(acc[0][0], a0, bq.x); ffma2(acc[0][1], a0, bq.y);
            ffma2(acc[1][0], a1, bq.x); ffma2(acc[1][1], a1, bq.y);
        }
        if (kt+1 < CATD/16) {
            const int q = p^1;
            if (tid < 128){
                As[q][akq*4+0][ar]=pa.x; As[q][akq*4+1][ar]=pa.y;
                As[q][akq*4+2][ar]=pa.z; As[q][akq*4+3][ar]=pa.w;
            }
            *(float4*)&Bs[q][bk][bn4*4] = pb;
        }
        __syncthreads();
    }
    const int n0 = nb + tn*4;
    float4 bv = *(const float4*)(bias1 + n0);
    #pragma unroll
    for (int i=0;i<2;i++){
        int row = rb + tm*2 + i;
        float2 l0 = unpk(acc[i][0]), l1 = unpk(acc[i][1]);
        float4 ccv = *(const float4*)(g_cc + (size_t)row*CATD + Xd + n0);
        float4 o;
        o.x = ccv.x * sigf(l0.x + bv.x);
        o.y = ccv.y * sigf(l0.y + bv.y);
        o.z = ccv.z * sigf(l1.x + bv.z);
        o.w = ccv.w * sigf(l1.y + bv.w);
        *(float4*)(g_cc2 + (size_t)row*CATD + Xd + n0) = o;
    }
}

// ---------------- big GEMM with fused LSTM / r epilogue (f32x2) ---------------------
// 256 threads, 64 rows x 16 quads, thread tile 4x4, double-buffered. grid (4,34).
__global__ __launch_bounds__(256) void k_big(const float* __restrict__ Wf,
                                             const float* __restrict__ bias,
                                             float* __restrict__ out, int t)
{
    __shared__ __align__(16) float As[2][16][68];
    __shared__ __align__(16) float Bs[2][16][64];
    const int tid = threadIdx.x;
    const int rb = blockIdx.x * 64;
    const int y = blockIdx.y;
    const bool isOm = (y >= 32);
    const int cb = isOm ? (2048 + (y-32)*64) : y*16;
    const int S  = isOm ? 16 : 512;
    const int tm = tid >> 4;   // rows group of 4
    const int tx = tid & 15;   // quad index

    ull acc[4][2] = {};

    const int ar = tid >> 2, akq = tid & 3;
    const float* Ap = g_cc2 + (size_t)(rb + ar)*CATD + akq*4;
    const int bk = tid >> 4, bg = (tid >> 2) & 3, bq4 = tid & 3;
    const float* Bp = Wf + (size_t)bk*NPRE + cb + S*bg + bq4*4;

    float4 pa = *(const float4*)Ap;
    float4 pb = *(const float4*)Bp;

    As[0][akq*4+0][ar]=pa.x; As[0][akq*4+1][ar]=pa.y;
    As[0][akq*4+2][ar]=pa.z; As[0][akq*4+3][ar]=pa.w;
    Bs[0][bk][(bq4*4+0)*4+bg]=pb.x; Bs[0][bk][(bq4*4+1)*4+bg]=pb.y;
    Bs[0][bk][(bq4*4+2)*4+bg]=pb.z; Bs[0][bk][(bq4*4+3)*4+bg]=pb.w;
    __syncthreads();

    for (int kt = 0; kt < CATD/16; kt++) {
        const int p = kt & 1;
        if (kt+1 < CATD/16) {
            int k0 = (kt+1)*16;
            pa = *(const float4*)(Ap + k0);
            pb = *(const float4*)(Bp + (size_t)k0*NPRE);
        }
        #pragma unroll
        for (int kk=0; kk<16; kk++){
            float4 av = *(const float4*)&As[p][kk][tm*4];
            ulonglong2 bq = *(const ulonglong2*)&Bs[p][kk][tx*4];
            ull a0 = pack2(av.x), a1 = pack2(av.y), a2 = pack2(av.z), a3 = pack2(av.w);
            ffma2(acc[0][0], a0, bq.x); ffma2(acc[0][1], a0, bq.y);
            ffma2(acc[1][0], a1, bq.x); ffma2(acc[1][1], a1, bq.y);
            ffma2(acc[2][0], a2, bq.x); ffma2(acc[2][1], a2, bq.y);
            ffma2(acc[3][0], a3, bq.x); ffma2(acc[3][1], a3, bq.y);
        }
        if (kt+1 < CATD/16) {
            const int q = p^1;
            As[q][akq*4+0][ar]=pa.x; As[q][akq*4+1][ar]=pa.y;
            As[q][akq*4+2][ar]=pa.z; As[q][akq*4+3][ar]=pa.w;
            Bs[q][bk][(bq4*4+0)*4+bg]=pb.x; Bs[q][bk][(bq4*4+1)*4+bg]=pb.y;
            Bs[q][bk][(bq4*4+2)*4+bg]=pb.z; Bs[q][bk][(bq4*4+3)*4+bg]=pb.w;
        }
        __syncthreads();
    }

    if (!isOm) {
        const int n = cb + tx;
        const float bi = bias[n], bj = bias[n+512], bf = bias[n+1024], bo = bias[n+1536];
        #pragma unroll
        for (int i=0;i<4;i++){
            int row = rb + tm*4 + i;
            float2 ij = unpk(acc[i][0]), fo = unpk(acc[i][1]);
            float c_old = g_c[row*Hd + n];
            float iv = ij.x+bi, jv = ij.y+bj, fv = fo.x+bf, ov = fo.y+bo;
            float nc = tanhf(c_old*sigf(fv + 1.0f) + sigf(iv)*tanhf(jv));
            g_c[row*Hd + n] = nc;
            out[(size_t)t*Bsz*ODIM + (size_t)row*ODIM + n] = nc * sigf(ov);
        }
    } else {
        #pragma unroll
        for (int i=0;i<4;i++){
            int row = rb + tm*4 + i;
            float2 g01 = unpk(acc[i][0]), g23 = unpk(acc[i][1]);
            float gv[4] = {g01.x, g01.y, g23.x, g23.y};
            #pragma unroll
            for (int g=0; g<4; g++){
                int mcol = (cb - 2048) + 16*g + tx;
                float rv = g_hent[row*Rd + mcol] * sigf(gv[g] + bias[2048 + mcol]);
                out[(size_t)t*Bsz*ODIM + (size_t)row*ODIM + Hd + mcol] = rv;
            }
        }
    }
}

// ---------------- tail: [head_c | wv] GEMM (K=512) + argmax + hmem scatter + gather
// grid 64 blocks x 256 threads; 4 batch rows per block. t in [-1, T-2].
__global__ __launch_bounds__(256) void k_tail(const float* __restrict__ x,
                                              const float* __restrict__ noise,
                                              const float* __restrict__ trans_b,
                                              int t)
{
    __shared__ float s_c[4][512];
    __shared__ float s_head[4][132];
    __shared__ float s_wv[4][132];
    __shared__ int   s_sel[4], s_selold[4];
    const int tid = threadIdx.x;
    const int warp = tid >> 5, lane = tid & 31;
    const int b0 = blockIdx.x * 4;
    const int tn = t + 1;

    #pragma unroll
    for (int j=0;j<2;j++){ int i = tid + 256*j; int r = i>>7, cc = i&127;
      *(float4*)&s_c[r][cc*4] = *(const float4*)(g_c + (b0+r)*Hd + cc*4); }
    if (tid < 4) s_selold[tid] = g_sel[b0+tid];
    __syncthreads();

    // GEMM: 4 rows x 256 cols (128 head_c | 128 wv), K=512 from s_c
    {
        const int rg = tid >> 6;          // 0..3 row
        const int c4 = (tid & 63) * 4;    // col group
        ull acc0 = 0, acc1 = 0;
        const float* wp = g_wcomb + c4;
        #pragma unroll 4
        for (int k = 0; k < Hd; k++){
            ull ap = pack2(s_c[rg][k]);
            ulonglong2 wq = *(const ulonglong2*)(wp + (size_t)k*256);
            ffma2(acc0, ap, wq.x);
            ffma2(acc1, ap, wq.y);
        }
        float2 l0 = unpk(acc0), l1 = unpk(acc1);
        float4 a = { l0.x, l0.y, l1.x, l1.y };
        if (c4 < 128) {
            float4 xh = *(const float4*)(g_xh + ((size_t)tn*Bsz + b0 + rg)*Md + c4);
            a.x += xh.x; a.y += xh.y; a.z += xh.z; a.w += xh.w;
            *(float4*)&s_head[rg][c4] = a;
        } else {
            int m4 = c4 - 128;
            float4 tb = *(const float4*)(trans_b + m4);
            a.x += tb.x; a.y += tb.y; a.z += tb.z; a.w += tb.w;
            *(float4*)&s_wv[rg][m4] = a;
        }
    }
    __syncthreads();

    // warps 0-3: gumbel + argmax; warps 4-7: hmem row write (t>=0)
    if (warp < 4) {
        int r = warp;
        float4 hv = *(const float4*)&s_head[r][lane*4];
        float4 nz = *(const float4*)(noise + ((size_t)tn*Bsz + b0 + r)*Md + lane*4);
        float v[4];
        v[0] = hv.x - logf(1e-20f - logf(1e-20f + nz.x));
        v[1] = hv.y - logf(1e-20f - logf(1e-20f + nz.y));
        v[2] = hv.z - logf(1e-20f - logf(1e-20f + nz.z));
        v[3] = hv.w - logf(1e-20f - logf(1e-20f + nz.w));
        float best = v[0]; int bi = lane*4;
        #pragma unroll
        for (int c=1;c<4;c++) if (v[c] > best){ best = v[c]; bi = lane*4+c; }
        #pragma unroll
        for (int off=16; off; off>>=1){
            float ov = __shfl_xor_sync(0xffffffffu, best, off);
            int   oi = __shfl_xor_sync(0xffffffffu, bi,   off);
            if (ov > best || (ov == best && oi < bi)){ best = ov; bi = oi; }
        }
        if (lane == 0) s_sel[r] = bi;
    } else if (t >= 0) {
        int r = warp - 4;
        float4 wv = *(const float4*)&s_wv[r][lane*4];
        int idx = (t < Md) ? t : s_selold[r];
        *(float4*)(g_hmem + ((size_t)(b0+r)*Md + idx)*Rd + lane*4) = wv;
    }
    __syncthreads();

    // gather h_entry for t+1, write cc / cc2 / sel
    if (warp < 4) {
        int r = warp;
        int sel = s_sel[r];
        float4 h4 = *(const float4*)(g_hmem + ((size_t)(b0+r)*Md + sel)*Rd + lane*4);
        *(float4*)(g_hent + (b0+r)*Rd + lane*4) = h4;
        *(float4*)(g_cc + (size_t)(b0+r)*CATD + XHD + lane*4) = h4;
        if (lane == 0) g_sel[b0+r] = sel;
    }
    { int r = tid>>6, cc = tid&63;
      float4 xv = *(const float4*)(x + ((size_t)tn*Bsz + b0 + r)*Xd + cc*4);
      *(float4*)(g_cc  + (size_t)(b0+r)*CATD + cc*4) = xv;
      *(float4*)(g_cc2 + (size_t)(b0+r)*CATD + cc*4) = xv; }
    #pragma unroll
    for (int j=0;j<2;j++){ int i = tid + 256*j; int r = i>>7, cc = i&127;
      *(float4*)(g_cc + (size_t)(b0+r)*CATD + Xd + cc*4) = *(const float4*)&s_c[r][cc*4]; }
}

extern "C" void kernel_launch(void* const* d_in, const int* in_sizes, int n_in,
                              void* d_out, int out_size)
{
    const float* x       = (const float*)d_in[0];
    const float* noise   = (const float*)d_in[1];
    const float* W_full  = (const float*)d_in[2];
    const float* bias    = (const float*)d_in[3];
    const float* W_full1 = (const float*)d_in[4];
    const float* bias1   = (const float*)d_in[5];
    const float* fc_w    = (const float*)d_in[6];
    const float* fc_b    = (const float*)d_in[7];
    const float* trans_w = (const float*)d_in[8];
    const float* trans_b = (const float*)d_in[9];
    const float* c_bias  = (const float*)d_in[10];
    const float* hmem_b  = (const float*)d_in[11];
    float* out = (float*)d_out;

    const int initN = Bsz*Md*Rd;
    k_init<<<(initN + 255)/256, 256>>>(fc_w, trans_w, c_bias, hmem_b);
    k_xhead<<<Td*Bsz/64, 256>>>(x, fc_b);
    k_tail<<<64, 256>>>(x, noise, trans_b, -1);   // prologue: head/argmax for t=0
    for (int t = 0; t < Td; t++){
        k_gates<<<dim3(8,10), 256>>>(W_full1, bias1);
        k_big  <<<dim3(4,34), 256>>>(W_full, bias, out, t);
        if (t < Td-1) k_tail<<<64, 256>>>(x, noise, trans_b, t);
    }
}